// round 8
// baseline (speedup 1.0000x reference)
#include <cuda_runtime.h>
#include <cstdint>

typedef unsigned long long u64;

// ---------- packed f32x2 helpers ----------
__device__ __forceinline__ u64 pk2(float lo, float hi) {
    u64 r;
    asm("mov.b64 %0, {%1, %2};" : "=l"(r)
        : "r"(__float_as_uint(lo)), "r"(__float_as_uint(hi)));
    return r;
}
__device__ __forceinline__ void upk(u64 a, float& lo, float& hi) {
    unsigned int l_, h_;
    asm("mov.b64 {%0, %1}, %2;" : "=r"(l_), "=r"(h_) : "l"(a));
    lo = __uint_as_float(l_);
    hi = __uint_as_float(h_);
}
__device__ __forceinline__ u64 dfma(u64 a, u64 b, u64 c) {
    u64 d;
    asm("fma.rn.f32x2 %0, %1, %2, %3;" : "=l"(d) : "l"(a), "l"(b), "l"(c));
    return d;
}
__device__ __forceinline__ u64 dmul(u64 a, u64 b) {
    u64 d;
    asm("mul.rn.f32x2 %0, %1, %2;" : "=l"(d) : "l"(a), "l"(b));
    return d;
}
__device__ __forceinline__ u64 dadd(u64 a, u64 b) {
    u64 d;
    asm("add.rn.f32x2 %0, %1, %2;" : "=l"(d) : "l"(a), "l"(b));
    return d;
}
// 2*relu(x) per half, exact: x + |x| (2x folded into pre-halved W2/W3)
__device__ __forceinline__ u64 drelu2(u64 a) {
    return dadd(a, a & 0x7FFFFFFF7FFFFFFFULL);
}
__device__ __forceinline__ uint32_t smem_u32(const void* p) {
    uint32_t a;
    asm("{ .reg .u64 t; cvta.to.shared.u64 t, %1; cvt.u32.u64 %0, t; }"
        : "=r"(a) : "l"(p));
    return a;
}
__device__ __forceinline__ void ldsw2(uint32_t addr, u64& a, u64& b) {
    asm("ld.shared.v2.u64 {%0, %1}, [%2];" : "=l"(a), "=l"(b) : "r"(addr));
}
__device__ __forceinline__ void lds_f2(uint32_t addr, float& a, float& b) {
    asm("ld.shared.v2.f32 {%0, %1}, [%2];" : "=f"(a), "=f"(b) : "r"(addr));
}
__device__ __forceinline__ void cp16(uint32_t dst, const char* src, bool pred) {
    if (pred)
        asm volatile("cp.async.cg.shared.global [%0], [%1], 16;"
                     :: "r"(dst), "l"(src) : "memory");
}
__device__ __forceinline__ void cp_commit() {
    asm volatile("cp.async.commit_group;" ::: "memory");
}
__device__ __forceinline__ void cp_wait2() {
    asm volatile("cp.async.wait_group 2;" ::: "memory");
}

// Weight smem layout (u64 packed (v,v)), ordered for paired loads:
//  [4j..4j+3] = W1[j,0..2], b1[j]   [20+6j..] = .5*W2[j,0..4], b2[j]
//  [50..55]   = .5*W3[0..4], b3
__device__ __forceinline__ void pair_step(
    u64 ax, u64 ay, u64 az,
    u64 npx, u64 npy, u64 npz,
    uint32_t swb,
    u64& vx, u64& vy, u64& vz)
{
    u64 dx = dadd(ax, npx);
    u64 dy = dadd(ay, npy);
    u64 dz = dadd(az, npz);
    u64 d2 = dfma(dx, dx, dfma(dy, dy, dmul(dz, dz)));
    float a, b;
    upk(d2, a, b);
    float ia = rsqrtf(fmaxf(a, 1e-24f));   // matches v/max(||v||,1e-12)
    float ib = rsqrtf(fmaxf(b, 1e-24f));

    // Layer 1 on the UNNORMALIZED diff (overlaps the MUFU rsqrt)
    u64 wa, wb, wc, B0, B1, B2, B3, B4;
    u64 u0, u1, u2, u3, u4;
    ldsw2(swb + 0 * 8, wa, wb); ldsw2(swb + 2 * 8, wc, B0);
    u0 = dfma(dz, wc, dfma(dy, wb, dmul(dx, wa)));
    ldsw2(swb + 4 * 8, wa, wb); ldsw2(swb + 6 * 8, wc, B1);
    u1 = dfma(dz, wc, dfma(dy, wb, dmul(dx, wa)));
    ldsw2(swb + 8 * 8, wa, wb); ldsw2(swb + 10 * 8, wc, B2);
    u2 = dfma(dz, wc, dfma(dy, wb, dmul(dx, wa)));
    ldsw2(swb + 12 * 8, wa, wb); ldsw2(swb + 14 * 8, wc, B3);
    u3 = dfma(dz, wc, dfma(dy, wb, dmul(dx, wa)));
    ldsw2(swb + 16 * 8, wa, wb); ldsw2(swb + 18 * 8, wc, B4);
    u4 = dfma(dz, wc, dfma(dy, wb, dmul(dx, wa)));

    u64 inv = pk2(ia, ib);
    u64 h0 = drelu2(dfma(u0, inv, B0));
    u64 h1 = drelu2(dfma(u1, inv, B1));
    u64 h2 = drelu2(dfma(u2, inv, B2));
    u64 h3 = drelu2(dfma(u3, inv, B3));
    u64 h4 = drelu2(dfma(u4, inv, B4));

    u64 wd, we, bj;
    u64 g0, g1, g2, g3, g4;
#define L2ROW(G, OFF)                                                       \
    ldsw2(swb + (OFF) * 8, wa, wb); ldsw2(swb + ((OFF) + 2) * 8, wc, wd);   \
    ldsw2(swb + ((OFF) + 4) * 8, we, bj);                                   \
    G = dfma(h0, wa, bj); G = dfma(h1, wb, G); G = dfma(h2, wc, G);         \
    G = dfma(h3, wd, G);  G = dfma(h4, we, G); G = drelu2(G);
    L2ROW(g0, 20) L2ROW(g1, 26) L2ROW(g2, 32) L2ROW(g3, 38) L2ROW(g4, 44)
#undef L2ROW

    ldsw2(swb + 50 * 8, wa, wb);
    ldsw2(swb + 52 * 8, wc, wd);
    ldsw2(swb + 54 * 8, we, bj);
    u64 wgt = dfma(g0, wa, bj);
    wgt = dfma(g1, wb, wgt); wgt = dfma(g2, wc, wgt);
    wgt = dfma(g3, wd, wgt); wgt = dfma(g4, we, wgt);

    u64 wi = dmul(wgt, inv);
    vx = dfma(dx, wi, vx);
    vy = dfma(dy, wi, vy);
    vz = dfma(dz, wi, vz);
}

// Warp-autonomous pipeline. Stage = 8 points x 32 neighbors = 3072B of
// CONTIGUOUS gmem (perfect cp.async coalescing). Ring depth 4 per warp.
// Lane = (point p = l&7, quarter q = l>>3); each lane runs pairs
// {q, q+4, q+8, q+12}; 2-round shfl_xor(8,16) reduce.
#define RING_D    4
#define PT_STRIDE 400u                 // 100 words: conflict-free v2 reads
#define STAGE_B   3200u                // 8 points * 400B
#define WARP_SMEM 12800u               // 4 stages
#define GROUP_GB  3072                 // 8 points * 384B in gmem

__global__ void __launch_bounds__(256, 2)
velvec_kernel(const float* __restrict__ pos, const float* __restrict__ nbr,
              const float* __restrict__ W1, const float* __restrict__ b1,
              const float* __restrict__ W2, const float* __restrict__ b2,
              const float* __restrict__ W3, const float* __restrict__ b3,
              float* __restrict__ out, int N, int ngroups)
{
    extern __shared__ char ring[];             // 8 warps * 12800 = 102400 B
    __shared__ __align__(16) u64 sw[56];

    int tid = threadIdx.x;

    // weights: load + pack + pre-scale once per block
    if (tid < 56) {
        float v;
        if (tid < 20) {
            int j = tid >> 2, i = tid & 3;
            v = (i < 3) ? __ldg(W1 + 3 * j + i) : __ldg(b1 + j);
        } else if (tid < 50) {
            int t = tid - 20, j = t / 6, i = t - 6 * j;
            v = (i < 5) ? 0.5f * __ldg(W2 + 5 * j + i) : __ldg(b2 + j);
        } else if (tid < 55) {
            v = 0.5f * __ldg(W3 + tid - 50);
        } else {
            v = __ldg(b3);
        }
        unsigned int u = __float_as_uint(v);
        sw[tid] = ((u64)u << 32) | (u64)u;
    }
    __syncthreads();

    int wid = tid >> 5;
    int l = tid & 31;
    int p = l & 7;             // point within 8-point group
    int q = l >> 3;            // quarter: pairs {q, q+4, q+8, q+12}
    uint32_t swb = smem_u32(sw);
    uint32_t wbase = smem_u32(ring) + (uint32_t)wid * WARP_SMEM;

    // cp.async chunk mapping: chunk m = l + 32c of the 3072B group slab;
    // smem dst is padded to 400B/point.
    uint32_t doff[6];
    int goff[6];
#pragma unroll
    for (int c = 0; c < 6; c++) {
        int m = l + 32 * c;
        int pp = m / 24, r = m % 24;
        doff[c] = (uint32_t)pp * PT_STRIDE + (uint32_t)r * 16u;
        goff[c] = m * 16;
    }

    int gw = blockIdx.x * 8 + wid;
    int GW = gridDim.x * 8;
    const char* gn = (const char*)nbr;
    long long nbytes = (long long)N * 384;

    // prologue: prefetch RING_D-1 groups
    int gq = gw;
#pragma unroll
    for (int k = 0; k < RING_D - 1; k++) {
        if (gq < ngroups) {
            long long base = (long long)gq * GROUP_GB;
#pragma unroll
            for (int c = 0; c < 6; c++)
                cp16(wbase + (uint32_t)k * STAGE_B + doff[c], gn + base + goff[c],
                     base + goff[c] + 16 <= nbytes);
        }
        cp_commit();
        gq += GW;
    }

    int s = 0;
    for (int g = gw; g < ngroups; g += GW) {
        cp_wait2();
        __syncwarp();

        int n = 8 * g + p;
        float px = 0.f, py = 0.f, pz = 0.f;
        if (n < N) {
            px = __ldg(pos + 3 * n + 0);
            py = __ldg(pos + 3 * n + 1);
            pz = __ldg(pos + 3 * n + 2);
        }
        u64 npx = pk2(-px, -px), npy = pk2(-py, -py), npz = pk2(-pz, -pz);
        u64 vx = 0ULL, vy = 0ULL, vz = 0ULL;

        uint32_t rowb = wbase + (uint32_t)s * STAGE_B + (uint32_t)p * PT_STRIDE;
#pragma unroll
        for (int jj = 0; jj < 4; jj++) {
            uint32_t sb = rowb + (uint32_t)(q + 4 * jj) * 24u;
            float x0, y0, z0, x1, y1, z1;
            lds_f2(sb + 0, x0, y0);
            lds_f2(sb + 8, z0, x1);
            lds_f2(sb + 16, y1, z1);
            pair_step(pk2(x0, x1), pk2(y0, y1), pk2(z0, z1),
                      npx, npy, npz, swb, vx, vy, vz);
        }

        float x0, x1, y0, y1, z0, z1;
        upk(vx, x0, x1); upk(vy, y0, y1); upk(vz, z0, z1);
        float fx = x0 + x1, fy = y0 + y1, fz = z0 + z1;
        fx += __shfl_xor_sync(0xFFFFFFFFu, fx, 8);
        fy += __shfl_xor_sync(0xFFFFFFFFu, fy, 8);
        fz += __shfl_xor_sync(0xFFFFFFFFu, fz, 8);
        fx += __shfl_xor_sync(0xFFFFFFFFu, fx, 16);
        fy += __shfl_xor_sync(0xFFFFFFFFu, fy, 16);
        fz += __shfl_xor_sync(0xFFFFFFFFu, fz, 16);

        if (q == 0 && n < N) {
            float d2 = fmaf(fx, fx, fmaf(fy, fy, fz * fz));
            d2 = fmaxf(d2, 1e-24f);
            float r = rsqrtf(d2);
            r = r * fmaf(-0.5f * d2 * r, r, 1.5f);  // one Newton step
            out[3 * n + 0] = fx * r;
            out[3 * n + 1] = fy * r;
            out[3 * n + 2] = fz * r;
        }

        __syncwarp();   // stage (s+3)&3 fully consumed; safe to refill
        if (gq < ngroups) {
            long long base = (long long)gq * GROUP_GB;
            uint32_t st = (uint32_t)((s + 3) & 3) * STAGE_B;
#pragma unroll
            for (int c = 0; c < 6; c++)
                cp16(wbase + st + doff[c], gn + base + goff[c],
                     base + goff[c] + 16 <= nbytes);
        }
        cp_commit();
        gq += GW;
        s = (s + 1) & 3;
    }
}

extern "C" void kernel_launch(void* const* d_in, const int* in_sizes, int n_in,
                              void* d_out, int out_size)
{
    const float* pos = (const float*)d_in[0];
    const float* nbr = (const float*)d_in[1];
    const float* W1  = (const float*)d_in[2];
    const float* b1  = (const float*)d_in[3];
    const float* W2  = (const float*)d_in[4];
    const float* b2  = (const float*)d_in[5];
    const float* W3  = (const float*)d_in[6];
    const float* b3  = (const float*)d_in[7];
    float* out = (float*)d_out;

    static bool attr_set = false;
    if (!attr_set) {
        cudaFuncSetAttribute(velvec_kernel,
                             cudaFuncAttributeMaxDynamicSharedMemorySize, 102400);
        attr_set = true;
    }

    int N = in_sizes[0] / 3;            // positions is [N,3]
    int ngroups = (N + 7) / 8;          // 8 points per warp-stage
    int grid = 296;                     // 2 persistent blocks per SM
    velvec_kernel<<<grid, 256, 102400>>>(pos, nbr, W1, b1, W2, b2, W3, b3,
                                         out, N, ngroups);
}

// round 9
// speedup vs baseline: 1.0224x; 1.0224x over previous
#include <cuda_runtime.h>
#include <cstdint>

typedef unsigned long long u64;

// ---------- packed f32x2 helpers ----------
__device__ __forceinline__ u64 pk2(float lo, float hi) {
    u64 r;
    asm("mov.b64 %0, {%1, %2};" : "=l"(r)
        : "r"(__float_as_uint(lo)), "r"(__float_as_uint(hi)));
    return r;
}
__device__ __forceinline__ void upk(u64 a, float& lo, float& hi) {
    unsigned int l_, h_;
    asm("mov.b64 {%0, %1}, %2;" : "=r"(l_), "=r"(h_) : "l"(a));
    lo = __uint_as_float(l_);
    hi = __uint_as_float(h_);
}
__device__ __forceinline__ u64 dfma(u64 a, u64 b, u64 c) {
    u64 d;
    asm("fma.rn.f32x2 %0, %1, %2, %3;" : "=l"(d) : "l"(a), "l"(b), "l"(c));
    return d;
}
__device__ __forceinline__ u64 dmul(u64 a, u64 b) {
    u64 d;
    asm("mul.rn.f32x2 %0, %1, %2;" : "=l"(d) : "l"(a), "l"(b));
    return d;
}
__device__ __forceinline__ u64 dadd(u64 a, u64 b) {
    u64 d;
    asm("add.rn.f32x2 %0, %1, %2;" : "=l"(d) : "l"(a), "l"(b));
    return d;
}
// 2*relu(x) per half, exact: x + |x| (2x folded into pre-halved W2/W3)
__device__ __forceinline__ u64 drelu2(u64 a) {
    return dadd(a, a & 0x7FFFFFFF7FFFFFFFULL);
}
__device__ __forceinline__ uint32_t smem_u32(const void* p) {
    uint32_t a;
    asm("{ .reg .u64 t; cvta.to.shared.u64 t, %1; cvt.u32.u64 %0, t; }"
        : "=r"(a) : "l"(p));
    return a;
}
__device__ __forceinline__ void ldsw2(uint32_t addr, u64& a, u64& b) {
    asm("ld.shared.v2.u64 {%0, %1}, [%2];" : "=l"(a), "=l"(b) : "r"(addr));
}
__device__ __forceinline__ void lds_f2(uint32_t addr, float& a, float& b) {
    asm("ld.shared.v2.f32 {%0, %1}, [%2];" : "=f"(a), "=f"(b) : "r"(addr));
}
__device__ __forceinline__ void sts64(uint32_t addr, u64 v) {
    asm volatile("st.shared.b64 [%0], %1;" :: "r"(addr), "l"(v) : "memory");
}

// Weight smem layout (u64 packed (v,v)):
//  [4j..4j+3] = W1[j,0..2], b1[j]   [20+6j..] = .5*W2[j,0..4], b2[j]
//  [50..55]   = .5*W3[0..4], b3
// Dual pair step: processes TWO packed pairs (A,B) sharing every weight load.
__device__ __forceinline__ void dual_step(
    u64 axA, u64 ayA, u64 azA,
    u64 axB, u64 ayB, u64 azB,
    u64 npx, u64 npy, u64 npz,
    uint32_t swb,
    u64& vx, u64& vy, u64& vz)
{
    u64 dxA = dadd(axA, npx), dyA = dadd(ayA, npy), dzA = dadd(azA, npz);
    u64 dxB = dadd(axB, npx), dyB = dadd(ayB, npy), dzB = dadd(azB, npz);
    u64 d2A = dfma(dxA, dxA, dfma(dyA, dyA, dmul(dzA, dzA)));
    u64 d2B = dfma(dxB, dxB, dfma(dyB, dyB, dmul(dzB, dzB)));
    float a0, a1, b0, b1;
    upk(d2A, a0, a1); upk(d2B, b0, b1);
    float iA0 = rsqrtf(fmaxf(a0, 1e-24f));   // matches v/max(||v||,1e-12)
    float iA1 = rsqrtf(fmaxf(a1, 1e-24f));
    float iB0 = rsqrtf(fmaxf(b0, 1e-24f));
    float iB1 = rsqrtf(fmaxf(b1, 1e-24f));

    // Layer 1 on UNNORMALIZED diffs (overlaps MUFU); weight loads shared A/B
    u64 wa, wb, wc, B0, B1, B2, B3, B4;
    u64 uA0, uA1, uA2, uA3, uA4, uB0, uB1, uB2, uB3, uB4;
    ldsw2(swb + 0,   wa, wb); ldsw2(swb + 16,  wc, B0);
    uA0 = dfma(dzA, wc, dfma(dyA, wb, dmul(dxA, wa)));
    uB0 = dfma(dzB, wc, dfma(dyB, wb, dmul(dxB, wa)));
    ldsw2(swb + 32,  wa, wb); ldsw2(swb + 48,  wc, B1);
    uA1 = dfma(dzA, wc, dfma(dyA, wb, dmul(dxA, wa)));
    uB1 = dfma(dzB, wc, dfma(dyB, wb, dmul(dxB, wa)));
    ldsw2(swb + 64,  wa, wb); ldsw2(swb + 80,  wc, B2);
    uA2 = dfma(dzA, wc, dfma(dyA, wb, dmul(dxA, wa)));
    uB2 = dfma(dzB, wc, dfma(dyB, wb, dmul(dxB, wa)));
    ldsw2(swb + 96,  wa, wb); ldsw2(swb + 112, wc, B3);
    uA3 = dfma(dzA, wc, dfma(dyA, wb, dmul(dxA, wa)));
    uB3 = dfma(dzB, wc, dfma(dyB, wb, dmul(dxB, wa)));
    ldsw2(swb + 128, wa, wb); ldsw2(swb + 144, wc, B4);
    uA4 = dfma(dzA, wc, dfma(dyA, wb, dmul(dxA, wa)));
    uB4 = dfma(dzB, wc, dfma(dyB, wb, dmul(dxB, wa)));

    u64 invA = pk2(iA0, iA1);
    u64 invB = pk2(iB0, iB1);

    u64 hA0 = drelu2(dfma(uA0, invA, B0)), hB0 = drelu2(dfma(uB0, invB, B0));
    u64 hA1 = drelu2(dfma(uA1, invA, B1)), hB1 = drelu2(dfma(uB1, invB, B1));
    u64 hA2 = drelu2(dfma(uA2, invA, B2)), hB2 = drelu2(dfma(uB2, invB, B2));
    u64 hA3 = drelu2(dfma(uA3, invA, B3)), hB3 = drelu2(dfma(uB3, invB, B3));
    u64 hA4 = drelu2(dfma(uA4, invA, B4)), hB4 = drelu2(dfma(uB4, invB, B4));

    // Layer 2 (weights pre-scaled by 0.5), loads shared A/B
    u64 wd, we, bj;
    u64 gA0, gA1, gA2, gA3, gA4, gB0, gB1, gB2, gB3, gB4;
#define L2ROW(GA, GB, OFF)                                                   \
    ldsw2(swb + (OFF) * 8, wa, wb); ldsw2(swb + ((OFF) + 2) * 8, wc, wd);    \
    ldsw2(swb + ((OFF) + 4) * 8, we, bj);                                    \
    GA = dfma(hA0, wa, bj); GA = dfma(hA1, wb, GA); GA = dfma(hA2, wc, GA);  \
    GA = dfma(hA3, wd, GA); GA = dfma(hA4, we, GA); GA = drelu2(GA);         \
    GB = dfma(hB0, wa, bj); GB = dfma(hB1, wb, GB); GB = dfma(hB2, wc, GB);  \
    GB = dfma(hB3, wd, GB); GB = dfma(hB4, we, GB); GB = drelu2(GB);
    L2ROW(gA0, gB0, 20) L2ROW(gA1, gB1, 26) L2ROW(gA2, gB2, 32)
    L2ROW(gA3, gB3, 38) L2ROW(gA4, gB4, 44)
#undef L2ROW

    // Layer 3 (pre-scaled by 0.5)
    ldsw2(swb + 50 * 8, wa, wb);
    ldsw2(swb + 52 * 8, wc, wd);
    ldsw2(swb + 54 * 8, we, bj);
    u64 wgA = dfma(gA0, wa, bj);
    wgA = dfma(gA1, wb, wgA); wgA = dfma(gA2, wc, wgA);
    wgA = dfma(gA3, wd, wgA); wgA = dfma(gA4, we, wgA);
    u64 wgB = dfma(gB0, wa, bj);
    wgB = dfma(gB1, wb, wgB); wgB = dfma(gB2, wc, wgB);
    wgB = dfma(gB3, wd, wgB); wgB = dfma(gB4, we, wgB);

    // vel += nd * w == d * (inv * w)
    u64 wiA = dmul(wgA, invA);
    u64 wiB = dmul(wgB, invB);
    vx = dfma(dxA, wiA, vx); vy = dfma(dyA, wiA, vy); vz = dfma(dzA, wiA, vz);
    vx = dfma(dxB, wiB, vx); vy = dfma(dyB, wiB, vy); vz = dfma(dzB, wiB, vz);
}

// Warp-local staging. Round = 8 points = 3072B contiguous gmem, 12 coalesced
// LDG.64 per warp -> warp-private smem (520B/point padded; pair slot = 32B).
// Lane = (p = l>>2, j = l&3) computes pairs {j, j+4, j+8, j+12} of point p
// via 2 dual_step calls; 2-step shfl_xor reduce over the 4 j-lanes.
#define PT_B     520u
#define WARP_B   (8u * PT_B)       // 4160
#define WARPS_PB 4

__global__ void __launch_bounds__(128, 4)
velvec_kernel(const float* __restrict__ pos, const float* __restrict__ nbr,
              const float* __restrict__ W1, const float* __restrict__ b1,
              const float* __restrict__ W2, const float* __restrict__ b2,
              const float* __restrict__ W3, const float* __restrict__ b3,
              float* __restrict__ out, int N, int ngroups)
{
    __shared__ __align__(16) u64 sw[56];
    __shared__ __align__(16) char buf[WARPS_PB * WARP_B];   // 16640 B

    int tid = threadIdx.x;

    // weights: load + pack + pre-scale once per block
    if (tid < 56) {
        float v;
        if (tid < 20) {
            int j = tid >> 2, i = tid & 3;
            v = (i < 3) ? __ldg(W1 + 3 * j + i) : __ldg(b1 + j);
        } else if (tid < 50) {
            int t = tid - 20, j = t / 6, i = t - 6 * j;
            v = (i < 5) ? 0.5f * __ldg(W2 + 5 * j + i) : __ldg(b2 + j);
        } else if (tid < 55) {
            v = 0.5f * __ldg(W3 + tid - 50);
        } else {
            v = __ldg(b3);
        }
        unsigned int u = __float_as_uint(v);
        sw[tid] = ((u64)u << 32) | (u64)u;
    }
    __syncthreads();

    int wid = tid >> 5;
    int l = tid & 31;
    int p = l >> 2;            // point 0..7
    int j = l & 3;             // pair lane 0..3
    uint32_t swb = smem_u32(sw);
    uint32_t wbase = smem_u32(buf) + (uint32_t)wid * WARP_B;

    // STS destination offsets for the 12 chunks (float2 f = 32c + l)
    uint32_t doff[12];
#pragma unroll
    for (int c = 0; c < 12; c++) {
        int f = 32 * c + l;
        int pp = f / 48, rr = f - 48 * pp;
        int pr = rr / 3, w = rr - 3 * pr;
        doff[c] = (uint32_t)pp * PT_B + (uint32_t)pr * 32u + (uint32_t)w * 8u;
    }
    // compute-side base for this lane's point/pair lane
    uint32_t cb = wbase + (uint32_t)p * PT_B + (uint32_t)j * 32u;

    int gw = blockIdx.x * 4 + wid;
    int GW = gridDim.x * 4;
    const char* gn = (const char*)nbr;
    long long nbytes = (long long)N * 384;

    u64 d[12];
    int g = gw;
    if (g < ngroups) {
        long long base = (long long)g * 3072;
#pragma unroll
        for (int c = 0; c < 12; c++) {
            long long off = base + (long long)(32 * c + l) * 8;
            d[c] = (off + 8 <= nbytes) ? __ldg((const u64*)(gn + off)) : 0ULL;
        }
#pragma unroll
        for (int c = 0; c < 12; c++) sts64(wbase + doff[c], d[c]);
    }
    __syncwarp();

    for (; g < ngroups; g += GW) {
        // prefetch next round's regs (LDG in flight over this round's compute)
        int g2 = g + GW;
        if (g2 < ngroups) {
            long long base = (long long)g2 * 3072;
#pragma unroll
            for (int c = 0; c < 12; c++) {
                long long off = base + (long long)(32 * c + l) * 8;
                if (off + 8 <= nbytes) d[c] = __ldg((const u64*)(gn + off));
            }
        }

        // ---- compute round g from warp smem ----
        int n = 8 * g + p;
        float px = 0.f, py = 0.f, pz = 0.f;
        if (n < N) {
            px = __ldg(pos + 3 * n + 0);
            py = __ldg(pos + 3 * n + 1);
            pz = __ldg(pos + 3 * n + 2);
        }
        u64 npx = pk2(-px, -px), npy = pk2(-py, -py), npz = pk2(-pz, -pz);
        u64 vx = 0ULL, vy = 0ULL, vz = 0ULL;

        {   // pairs j and j+4
            float xa0, ya0, za0, xa1, ya1, za1;
            float xb0, yb0, zb0, xb1, yb1, zb1;
            lds_f2(cb + 0,   xa0, ya0); lds_f2(cb + 8,   za0, xa1); lds_f2(cb + 16,  ya1, za1);
            lds_f2(cb + 128, xb0, yb0); lds_f2(cb + 136, zb0, xb1); lds_f2(cb + 144, yb1, zb1);
            dual_step(pk2(xa0, xa1), pk2(ya0, ya1), pk2(za0, za1),
                      pk2(xb0, xb1), pk2(yb0, yb1), pk2(zb0, zb1),
                      npx, npy, npz, swb, vx, vy, vz);
        }
        {   // pairs j+8 and j+12
            float xa0, ya0, za0, xa1, ya1, za1;
            float xb0, yb0, zb0, xb1, yb1, zb1;
            lds_f2(cb + 256, xa0, ya0); lds_f2(cb + 264, za0, xa1); lds_f2(cb + 272, ya1, za1);
            lds_f2(cb + 384, xb0, yb0); lds_f2(cb + 392, zb0, xb1); lds_f2(cb + 400, yb1, zb1);
            dual_step(pk2(xa0, xa1), pk2(ya0, ya1), pk2(za0, za1),
                      pk2(xb0, xb1), pk2(yb0, yb1), pk2(zb0, zb1),
                      npx, npy, npz, swb, vx, vy, vz);
        }

        float x0, x1, y0, y1, z0, z1;
        upk(vx, x0, x1); upk(vy, y0, y1); upk(vz, z0, z1);
        float fx = x0 + x1, fy = y0 + y1, fz = z0 + z1;
        fx += __shfl_xor_sync(0xFFFFFFFFu, fx, 1);
        fy += __shfl_xor_sync(0xFFFFFFFFu, fy, 1);
        fz += __shfl_xor_sync(0xFFFFFFFFu, fz, 1);
        fx += __shfl_xor_sync(0xFFFFFFFFu, fx, 2);
        fy += __shfl_xor_sync(0xFFFFFFFFu, fy, 2);
        fz += __shfl_xor_sync(0xFFFFFFFFu, fz, 2);

        if (j == 0 && n < N) {
            float d2 = fmaf(fx, fx, fmaf(fy, fy, fz * fz));
            d2 = fmaxf(d2, 1e-24f);
            float r = rsqrtf(d2);
            r = r * fmaf(-0.5f * d2 * r, r, 1.5f);  // one Newton step
            out[3 * n + 0] = fx * r;
            out[3 * n + 1] = fy * r;
            out[3 * n + 2] = fz * r;
        }

        // ---- stage next round ----
        __syncwarp();          // all lanes done reading this round
        if (g2 < ngroups) {
#pragma unroll
            for (int c = 0; c < 12; c++) sts64(wbase + doff[c], d[c]);
        }
        __syncwarp();          // staged data visible to all lanes
    }
}

extern "C" void kernel_launch(void* const* d_in, const int* in_sizes, int n_in,
                              void* d_out, int out_size)
{
    const float* pos = (const float*)d_in[0];
    const float* nbr = (const float*)d_in[1];
    const float* W1  = (const float*)d_in[2];
    const float* b1  = (const float*)d_in[3];
    const float* W2  = (const float*)d_in[4];
    const float* b2  = (const float*)d_in[5];
    const float* W3  = (const float*)d_in[6];
    const float* b3  = (const float*)d_in[7];
    float* out = (float*)d_out;

    int N = in_sizes[0] / 3;            // positions is [N,3]
    int ngroups = (N + 7) / 8;          // 8 points per warp-round
    int grid = 592;                     // 4 persistent blocks per SM
    velvec_kernel<<<grid, 128>>>(pos, nbr, W1, b1, W2, b2, W3, b3,
                                 out, N, ngroups);
}

// round 10
// speedup vs baseline: 2.0309x; 1.9864x over previous
#include <cuda_runtime.h>
#include <cstdint>

typedef unsigned long long u64;

// ---------- packed f32x2 helpers ----------
__device__ __forceinline__ u64 pk2(float lo, float hi) {
    u64 r;
    asm("mov.b64 %0, {%1, %2};" : "=l"(r)
        : "r"(__float_as_uint(lo)), "r"(__float_as_uint(hi)));
    return r;
}
__device__ __forceinline__ void upk(u64 a, float& lo, float& hi) {
    unsigned int l_, h_;
    asm("mov.b64 {%0, %1}, %2;" : "=r"(l_), "=r"(h_) : "l"(a));
    lo = __uint_as_float(l_);
    hi = __uint_as_float(h_);
}
__device__ __forceinline__ u64 dfma(u64 a, u64 b, u64 c) {
    u64 d;
    asm("fma.rn.f32x2 %0, %1, %2, %3;" : "=l"(d) : "l"(a), "l"(b), "l"(c));
    return d;
}
__device__ __forceinline__ u64 dmul(u64 a, u64 b) {
    u64 d;
    asm("mul.rn.f32x2 %0, %1, %2;" : "=l"(d) : "l"(a), "l"(b));
    return d;
}
__device__ __forceinline__ u64 dadd(u64 a, u64 b) {
    u64 d;
    asm("add.rn.f32x2 %0, %1, %2;" : "=l"(d) : "l"(a), "l"(b));
    return d;
}
// 2*relu(x) per half, exact: x + |x| (2x folded into pre-halved W2/W3)
__device__ __forceinline__ u64 drelu2(u64 a) {
    return dadd(a, a & 0x7FFFFFFF7FFFFFFFULL);
}
__device__ __forceinline__ uint32_t smem_u32(const void* p) {
    uint32_t a;
    asm("{ .reg .u64 t; cvta.to.shared.u64 t, %1; cvt.u32.u64 %0, t; }"
        : "=r"(a) : "l"(p));
    return a;
}
__device__ __forceinline__ void ldsw2(uint32_t addr, u64& a, u64& b) {
    asm("ld.shared.v2.u64 {%0, %1}, [%2];" : "=l"(a), "=l"(b) : "r"(addr));
}
__device__ __forceinline__ void lds128(uint32_t addr, float4& q) {
    asm("ld.shared.v4.f32 {%0, %1, %2, %3}, [%4];"
        : "=f"(q.x), "=f"(q.y), "=f"(q.z), "=f"(q.w) : "r"(addr));
}
__device__ __forceinline__ void cp16(uint32_t dst, const char* src) {
    asm volatile("cp.async.cg.shared.global [%0], [%1], 16;"
                 :: "r"(dst), "l"(src) : "memory");
}
__device__ __forceinline__ void cp16p(uint32_t dst, const char* src, bool pred) {
    if (pred)
        asm volatile("cp.async.cg.shared.global [%0], [%1], 16;"
                     :: "r"(dst), "l"(src) : "memory");
}
__device__ __forceinline__ void cp_commit() {
    asm volatile("cp.async.commit_group;" ::: "memory");
}
__device__ __forceinline__ void cp_wait1() {
    asm volatile("cp.async.wait_group 1;" ::: "memory");
}

// Weight smem layout (u64 packed (v,v)):
//  [4j..4j+3] = W1[j,0..2], b1[j]   [20+6j..] = .5*W2[j,0..4], b2[j]
//  [50..55]   = .5*W3[0..4], b3
// Dual pair step: TWO packed pairs (A,B) share every weight load (7 LDS/pair).
__device__ __forceinline__ void dual_step(
    u64 axA, u64 ayA, u64 azA,
    u64 axB, u64 ayB, u64 azB,
    u64 npx, u64 npy, u64 npz,
    uint32_t swb,
    u64& vx, u64& vy, u64& vz)
{
    u64 dxA = dadd(axA, npx), dyA = dadd(ayA, npy), dzA = dadd(azA, npz);
    u64 dxB = dadd(axB, npx), dyB = dadd(ayB, npy), dzB = dadd(azB, npz);
    u64 d2A = dfma(dxA, dxA, dfma(dyA, dyA, dmul(dzA, dzA)));
    u64 d2B = dfma(dxB, dxB, dfma(dyB, dyB, dmul(dzB, dzB)));
    float a0, a1, b0, b1;
    upk(d2A, a0, a1); upk(d2B, b0, b1);
    float iA0 = rsqrtf(fmaxf(a0, 1e-24f));   // matches v/max(||v||,1e-12)
    float iA1 = rsqrtf(fmaxf(a1, 1e-24f));
    float iB0 = rsqrtf(fmaxf(b0, 1e-24f));
    float iB1 = rsqrtf(fmaxf(b1, 1e-24f));

    // Layer 1 on UNNORMALIZED diffs (overlaps MUFU); weight loads shared A/B
    u64 wa, wb, wc, B0, B1, B2, B3, B4;
    u64 uA0, uA1, uA2, uA3, uA4, uB0, uB1, uB2, uB3, uB4;
    ldsw2(swb + 0,   wa, wb); ldsw2(swb + 16,  wc, B0);
    uA0 = dfma(dzA, wc, dfma(dyA, wb, dmul(dxA, wa)));
    uB0 = dfma(dzB, wc, dfma(dyB, wb, dmul(dxB, wa)));
    ldsw2(swb + 32,  wa, wb); ldsw2(swb + 48,  wc, B1);
    uA1 = dfma(dzA, wc, dfma(dyA, wb, dmul(dxA, wa)));
    uB1 = dfma(dzB, wc, dfma(dyB, wb, dmul(dxB, wa)));
    ldsw2(swb + 64,  wa, wb); ldsw2(swb + 80,  wc, B2);
    uA2 = dfma(dzA, wc, dfma(dyA, wb, dmul(dxA, wa)));
    uB2 = dfma(dzB, wc, dfma(dyB, wb, dmul(dxB, wa)));
    ldsw2(swb + 96,  wa, wb); ldsw2(swb + 112, wc, B3);
    uA3 = dfma(dzA, wc, dfma(dyA, wb, dmul(dxA, wa)));
    uB3 = dfma(dzB, wc, dfma(dyB, wb, dmul(dxB, wa)));
    ldsw2(swb + 128, wa, wb); ldsw2(swb + 144, wc, B4);
    uA4 = dfma(dzA, wc, dfma(dyA, wb, dmul(dxA, wa)));
    uB4 = dfma(dzB, wc, dfma(dyB, wb, dmul(dxB, wa)));

    u64 invA = pk2(iA0, iA1);
    u64 invB = pk2(iB0, iB1);

    u64 hA0 = drelu2(dfma(uA0, invA, B0)), hB0 = drelu2(dfma(uB0, invB, B0));
    u64 hA1 = drelu2(dfma(uA1, invA, B1)), hB1 = drelu2(dfma(uB1, invB, B1));
    u64 hA2 = drelu2(dfma(uA2, invA, B2)), hB2 = drelu2(dfma(uB2, invB, B2));
    u64 hA3 = drelu2(dfma(uA3, invA, B3)), hB3 = drelu2(dfma(uB3, invB, B3));
    u64 hA4 = drelu2(dfma(uA4, invA, B4)), hB4 = drelu2(dfma(uB4, invB, B4));

    // Layer 2 (weights pre-scaled by 0.5), loads shared A/B
    u64 wd, we, bj;
    u64 gA0, gA1, gA2, gA3, gA4, gB0, gB1, gB2, gB3, gB4;
#define L2ROW(GA, GB, OFF)                                                   \
    ldsw2(swb + (OFF) * 8, wa, wb); ldsw2(swb + ((OFF) + 2) * 8, wc, wd);    \
    ldsw2(swb + ((OFF) + 4) * 8, we, bj);                                    \
    GA = dfma(hA0, wa, bj); GA = dfma(hA1, wb, GA); GA = dfma(hA2, wc, GA);  \
    GA = dfma(hA3, wd, GA); GA = dfma(hA4, we, GA); GA = drelu2(GA);         \
    GB = dfma(hB0, wa, bj); GB = dfma(hB1, wb, GB); GB = dfma(hB2, wc, GB);  \
    GB = dfma(hB3, wd, GB); GB = dfma(hB4, we, GB); GB = drelu2(GB);
    L2ROW(gA0, gB0, 20) L2ROW(gA1, gB1, 26) L2ROW(gA2, gB2, 32)
    L2ROW(gA3, gB3, 38) L2ROW(gA4, gB4, 44)
#undef L2ROW

    // Layer 3 (pre-scaled by 0.5)
    ldsw2(swb + 50 * 8, wa, wb);
    ldsw2(swb + 52 * 8, wc, wd);
    ldsw2(swb + 54 * 8, we, bj);
    u64 wgA = dfma(gA0, wa, bj);
    wgA = dfma(gA1, wb, wgA); wgA = dfma(gA2, wc, wgA);
    wgA = dfma(gA3, wd, wgA); wgA = dfma(gA4, we, wgA);
    u64 wgB = dfma(gB0, wa, bj);
    wgB = dfma(gB1, wb, wgB); wgB = dfma(gB2, wc, wgB);
    wgB = dfma(gB3, wd, wgB); wgB = dfma(gB4, we, wgB);

    // vel += nd * w == d * (inv * w)
    u64 wiA = dmul(wgA, invA);
    u64 wiB = dmul(wgB, invB);
    vx = dfma(dxA, wiA, vx); vy = dfma(dyA, wiA, vy); vz = dfma(dzA, wiA, vz);
    vx = dfma(dxB, wiB, vx); vy = dfma(dyB, wiB, vy); vz = dfma(dzB, wiB, vz);
}

// Persistent blocks, double-buffered block staging.
// Tile = 128 points (49152B gmem -> 51200B smem, 400B/pt padded stride:
// conflict-free LDS.128 across 8-lane phases). 256 threads: warp w covers
// points w*16+(l&15); half l>>4 takes 16 neighbors; shfl_xor(16) reduce.
#define TILE_PTS 128
#define PT_B     400u
#define BUF_B    51200u
#define TILE_GB  49152LL

__device__ __forceinline__ void stage_tile_full(uint32_t dstb, const char* gn,
                                                long long t, int tid) {
    long long src = t * TILE_GB;
#pragma unroll
    for (int c = 0; c < 12; c++) {
        int m = tid + 256 * c;
        int pp = m / 24, r = m - pp * 24;
        cp16(dstb + (uint32_t)pp * PT_B + (uint32_t)r * 16u,
             gn + src + (long long)m * 16);
    }
}
__device__ __forceinline__ void stage_tile_pred(uint32_t dstb, const char* gn,
                                                long long t, int tid,
                                                long long nbytes) {
    long long src = t * TILE_GB;
#pragma unroll
    for (int c = 0; c < 12; c++) {
        int m = tid + 256 * c;
        int pp = m / 24, r = m - pp * 24;
        long long off = src + (long long)m * 16;
        cp16p(dstb + (uint32_t)pp * PT_B + (uint32_t)r * 16u,
              gn + off, off + 16 <= nbytes);
    }
}

__global__ void __launch_bounds__(256, 2)
velvec_kernel(const float* __restrict__ pos, const float* __restrict__ nbr,
              const float* __restrict__ W1, const float* __restrict__ b1,
              const float* __restrict__ W2, const float* __restrict__ b2,
              const float* __restrict__ W3, const float* __restrict__ b3,
              float* __restrict__ out, int N, int ntiles)
{
    extern __shared__ char buf[];              // 2 * 51200 B
    __shared__ __align__(16) u64 sw[56];

    int tid = threadIdx.x;

    // weights: load + pack + pre-scale once per block
    if (tid < 56) {
        float v;
        if (tid < 20) {
            int j = tid >> 2, i = tid & 3;
            v = (i < 3) ? __ldg(W1 + 3 * j + i) : __ldg(b1 + j);
        } else if (tid < 50) {
            int t = tid - 20, j = t / 6, i = t - 6 * j;
            v = (i < 5) ? 0.5f * __ldg(W2 + 5 * j + i) : __ldg(b2 + j);
        } else if (tid < 55) {
            v = 0.5f * __ldg(W3 + tid - 50);
        } else {
            v = __ldg(b3);
        }
        unsigned int u = __float_as_uint(v);
        sw[tid] = ((u64)u << 32) | (u64)u;
    }
    __syncthreads();

    uint32_t swb = smem_u32(sw);
    uint32_t bufb = smem_u32(buf);
    const char* gn = (const char*)nbr;
    long long nbytes = (long long)N * 384;

    int w = tid >> 5;
    int l = tid & 31;
    int p = (w & 7) * 16 + (l & 15);     // point in tile (warp covers 16 pts)
    int half = l >> 4;                    // neighbor half (16 each)

    int G = gridDim.x;
    int full = ntiles - 1;               // tiles [0, full) are complete

    // prologue: stage tiles t0, t0+G
    {
        long long t0 = blockIdx.x;
        if (t0 < ntiles) {
            if (t0 < full) stage_tile_full(bufb, gn, t0, tid);
            else           stage_tile_pred(bufb, gn, t0, tid, nbytes);
        }
        cp_commit();
        long long t1 = t0 + G;
        if (t1 < ntiles) {
            if (t1 < full) stage_tile_full(bufb + BUF_B, gn, t1, tid);
            else           stage_tile_pred(bufb + BUF_B, gn, t1, tid, nbytes);
        }
        cp_commit();
    }

    int k = 0;
    for (long long t = blockIdx.x; t < ntiles; t += G, k++) {
        cp_wait1();          // this tile's group complete (next may be in flight)
        __syncthreads();     // cross-thread visibility of staged data

        uint32_t myb = bufb + (uint32_t)(k & 1) * BUF_B;
        int n = (int)(t * TILE_PTS) + p;

        float px = 0.f, py = 0.f, pz = 0.f;
        if (n < N) {
            px = __ldg(pos + 3 * n + 0);
            py = __ldg(pos + 3 * n + 1);
            pz = __ldg(pos + 3 * n + 2);
        }
        u64 npx = pk2(-px, -px), npy = pk2(-py, -py), npz = pk2(-pz, -pz);
        u64 vx = 0ULL, vy = 0ULL, vz = 0ULL;

        uint32_t rb = myb + (uint32_t)p * PT_B + (uint32_t)half * 192u;
#pragma unroll
        for (int gi = 0; gi < 4; gi++) {
            float4 q0, q1, q2;       // 4 neighbors = 2 packed pairs
            lds128(rb + gi * 48u + 0u,  q0);
            lds128(rb + gi * 48u + 16u, q1);
            lds128(rb + gi * 48u + 32u, q2);
            dual_step(pk2(q0.x, q0.w), pk2(q0.y, q1.x), pk2(q0.z, q1.y),
                      pk2(q1.z, q2.y), pk2(q1.w, q2.z), pk2(q2.x, q2.w),
                      npx, npy, npz, swb, vx, vy, vz);
        }

        float x0, x1, y0, y1, z0, z1;
        upk(vx, x0, x1); upk(vy, y0, y1); upk(vz, z0, z1);
        float fx = x0 + x1, fy = y0 + y1, fz = z0 + z1;
        fx += __shfl_xor_sync(0xFFFFFFFFu, fx, 16);
        fy += __shfl_xor_sync(0xFFFFFFFFu, fy, 16);
        fz += __shfl_xor_sync(0xFFFFFFFFu, fz, 16);

        if (half == 0 && n < N) {
            float d2 = fmaf(fx, fx, fmaf(fy, fy, fz * fz));
            d2 = fmaxf(d2, 1e-24f);
            float r = rsqrtf(d2);
            r = r * fmaf(-0.5f * d2 * r, r, 1.5f);  // one Newton step
            out[3 * n + 0] = fx * r;
            out[3 * n + 1] = fy * r;
            out[3 * n + 2] = fz * r;
        }

        __syncthreads();     // all threads done reading buffer (k&1)
        long long t2 = t + 2 * G;
        if (t2 < ntiles) {
            if (t2 < full) stage_tile_full(myb, gn, t2, tid);
            else           stage_tile_pred(myb, gn, t2, tid, nbytes);
        }
        cp_commit();         // one group per iteration keeps wait_group 1 exact
    }
}

extern "C" void kernel_launch(void* const* d_in, const int* in_sizes, int n_in,
                              void* d_out, int out_size)
{
    const float* pos = (const float*)d_in[0];
    const float* nbr = (const float*)d_in[1];
    const float* W1  = (const float*)d_in[2];
    const float* b1  = (const float*)d_in[3];
    const float* W2  = (const float*)d_in[4];
    const float* b2  = (const float*)d_in[5];
    const float* W3  = (const float*)d_in[6];
    const float* b3  = (const float*)d_in[7];
    float* out = (float*)d_out;

    static bool attr_set = false;
    if (!attr_set) {
        cudaFuncSetAttribute(velvec_kernel,
                             cudaFuncAttributeMaxDynamicSharedMemorySize, 102400);
        attr_set = true;
    }

    int N = in_sizes[0] / 3;            // positions is [N,3]
    int ntiles = (N + TILE_PTS - 1) / TILE_PTS;
    int grid = 296;                     // 2 persistent blocks per SM
    if (grid > ntiles) grid = ntiles;
    velvec_kernel<<<grid, 256, 102400>>>(pos, nbr, W1, b1, W2, b2, W3, b3,
                                         out, N, ntiles);
}